// round 10
// baseline (speedup 1.0000x reference)
#include <cuda_runtime.h>
#include <cuda_bf16.h>
#include <math.h>

// Problem constants: B=32, T=512, D=H=512, L=2
// Inputs (metadata order): x, Wr, br, Wu, bu, Wo, bo
// Output: (L, B, H) float32 = 32768 elements.

#define T_LEN 512
#define BATCH 32
#define HID   512

// ---------------- device scratch (no cudaMalloc allowed) ----------------
__device__ float    g_XP[(size_t)16384 * 1536];   // x-projections [m=t*32+b][n=g*512+j], g:0=u,1=r,2=o
__device__ float    g_Hseq[(size_t)16384 * 512];  // layer-0 hidden sequence [m=t*32+b][j]
__device__ float    g_hbuf[2][BATCH * HID];       // ping-pong h, [b][j]
__device__ float    g_hr[BATCH * HID];            // h*r exchange, [b][j]
__device__ unsigned g_bar[4 * 32];                // per-batch-group barriers, 128B apart

// bf16-split scratch for tensor-core xproj
__device__ __nv_bfloat16 g_Ah[(size_t)16384 * 512];
__device__ __nv_bfloat16 g_Al[(size_t)16384 * 512];
__device__ __nv_bfloat16 g_Wh[(size_t)3 * 512 * 512];
__device__ __nv_bfloat16 g_Wl[(size_t)3 * 512 * 512];

__global__ void reset_kernel() {
    if (threadIdx.x < 128) g_bar[threadIdx.x] = 0u;
}

// ============================================================================
// fp32 -> (bf16 hi, bf16 lo) conversion kernels
// ============================================================================
__device__ __forceinline__ void split_bf16(float v, __nv_bfloat16& hi, __nv_bfloat16& lo) {
    hi = __float2bfloat16(v);
    lo = __float2bfloat16(v - __bfloat162float(hi));
}

// A matrix: 16384 x 512.  amode 0: from x[b][t][k] (m = t*32+b). amode 1: from g_Hseq (row-major).
__global__ __launch_bounds__(256) void convA_kernel(const float* __restrict__ x, int amode) {
    size_t idx = ((size_t)blockIdx.x * 256 + threadIdx.x) * 4;
    int m = (int)(idx >> 9);
    int k = (int)(idx & 511);
    const float* src = amode ? (g_Hseq + idx)
                             : (x + ((size_t)(m & 31) * 512 + (m >> 5)) * 512 + k);
    float4 v = *(const float4*)src;
    __nv_bfloat16 h0, h1, h2, h3, l0, l1, l2, l3;
    split_bf16(v.x, h0, l0); split_bf16(v.y, h1, l1);
    split_bf16(v.z, h2, l2); split_bf16(v.w, h3, l3);
    ((__nv_bfloat162*)(g_Ah + idx))[0] = __nv_bfloat162(h0, h1);
    ((__nv_bfloat162*)(g_Ah + idx))[1] = __nv_bfloat162(h2, h3);
    ((__nv_bfloat162*)(g_Al + idx))[0] = __nv_bfloat162(l0, l1);
    ((__nv_bfloat162*)(g_Al + idx))[1] = __nv_bfloat162(l2, l3);
}

// W x-halves: g (0=u,1=r,2=o) x 512 j x 512 k  (source row stride 1024)
__global__ __launch_bounds__(256) void convW_kernel(
    const float* __restrict__ Wr, const float* __restrict__ Wu, const float* __restrict__ Wo) {
    size_t idx = ((size_t)blockIdx.x * 256 + threadIdx.x) * 4;   // over 3*512*512
    int g = (int)(idx >> 18);
    int r = (int)(idx & 262143);
    int j = r >> 9, k = r & 511;
    const float* W = (g == 0) ? Wu : (g == 1) ? Wr : Wo;
    float4 v = *(const float4*)(W + (size_t)j * 1024 + k);
    __nv_bfloat16 h0, h1, h2, h3, l0, l1, l2, l3;
    split_bf16(v.x, h0, l0); split_bf16(v.y, h1, l1);
    split_bf16(v.z, h2, l2); split_bf16(v.w, h3, l3);
    ((__nv_bfloat162*)(g_Wh + idx))[0] = __nv_bfloat162(h0, h1);
    ((__nv_bfloat162*)(g_Wh + idx))[1] = __nv_bfloat162(h2, h3);
    ((__nv_bfloat162*)(g_Wl + idx))[0] = __nv_bfloat162(l0, l1);
    ((__nv_bfloat162*)(g_Wl + idx))[1] = __nv_bfloat162(l2, l3);
}

// ============================================================================
// Tensor-core xproj:  g_XP[m][n] = A[m][:] . W[n][:] + b[n]
// bf16-split: AhWh + AhWl + AlWh, fp32 accumulate.
// BM=128, BN=64, BK=32, 256 threads = 8 warps (4m x 2n), warp tile 32x32.
// ============================================================================
__device__ __forceinline__ void ldsm_x4(unsigned& r0, unsigned& r1, unsigned& r2, unsigned& r3,
                                        const __nv_bfloat16* p) {
    unsigned a = (unsigned)__cvta_generic_to_shared(p);
    asm volatile("ldmatrix.sync.aligned.m8n8.x4.shared.b16 {%0,%1,%2,%3}, [%4];"
                 : "=r"(r0), "=r"(r1), "=r"(r2), "=r"(r3) : "r"(a));
}

__device__ __forceinline__ void mma_bf16(float* c, const unsigned* a, const unsigned* b) {
    asm volatile("mma.sync.aligned.m16n8k16.row.col.f32.bf16.bf16.f32 "
                 "{%0,%1,%2,%3}, {%4,%5,%6,%7}, {%8,%9}, {%0,%1,%2,%3};"
                 : "+f"(c[0]), "+f"(c[1]), "+f"(c[2]), "+f"(c[3])
                 : "r"(a[0]), "r"(a[1]), "r"(a[2]), "r"(a[3]), "r"(b[0]), "r"(b[1]));
}

#define SM_PITCH 40   // 32 + 8 bf16 pad (16B) -> ldmatrix conflict-free

__global__ __launch_bounds__(256) void xproj_mma_kernel(
    const float* __restrict__ br, const float* __restrict__ bu, const float* __restrict__ bo) {
    __shared__ __nv_bfloat16 Ah_s[128][SM_PITCH];
    __shared__ __nv_bfloat16 Al_s[128][SM_PITCH];
    __shared__ __nv_bfloat16 Wh_s[64][SM_PITCH];
    __shared__ __nv_bfloat16 Wl_s[64][SM_PITCH];

    int tid = threadIdx.x;
    int m0 = blockIdx.x * 128;
    int n0 = blockIdx.y * 64;
    int g = n0 >> 9, j0 = n0 & 511;
    const float* bv = (g == 0) ? bu : (g == 1) ? br : bo;

    int w = tid >> 5, lane = tid & 31;
    int wm = w >> 1, wn = w & 1;

    float acc[2][4][4];
#pragma unroll
    for (int mf = 0; mf < 2; mf++)
#pragma unroll
        for (int nf = 0; nf < 4; nf++)
#pragma unroll
            for (int i = 0; i < 4; i++) acc[mf][nf][i] = 0.f;

    for (int k0 = 0; k0 < 512; k0 += 32) {
#pragma unroll
        for (int q = 0; q < 2; q++) {
            int u = q * 256 + tid;
            int row = u >> 2, c8 = (u & 3) * 8;
            size_t go = (size_t)(m0 + row) * 512 + k0 + c8;
            *(uint4*)&Ah_s[row][c8] = *(const uint4*)(g_Ah + go);
            *(uint4*)&Al_s[row][c8] = *(const uint4*)(g_Al + go);
        }
        {
            int row = tid >> 2, c8 = (tid & 3) * 8;
            size_t go = ((size_t)g * 512 + j0 + row) * 512 + k0 + c8;
            *(uint4*)&Wh_s[row][c8] = *(const uint4*)(g_Wh + go);
            *(uint4*)&Wl_s[row][c8] = *(const uint4*)(g_Wl + go);
        }
        __syncthreads();

#pragma unroll
        for (int k16 = 0; k16 < 32; k16 += 16) {
            unsigned ah[2][4], al[2][4], bh[4][2], bl[4][2];
            int arow = wm * 32 + (lane & 15);
            int acol = k16 + (lane >> 4) * 8;
#pragma unroll
            for (int mf = 0; mf < 2; mf++) {
                ldsm_x4(ah[mf][0], ah[mf][1], ah[mf][2], ah[mf][3], &Ah_s[arow + mf * 16][acol]);
                ldsm_x4(al[mf][0], al[mf][1], al[mf][2], al[mf][3], &Al_s[arow + mf * 16][acol]);
            }
            int brow_ = ((lane & 16) >> 1) + (lane & 7);
            int bcol = k16 + ((lane >> 3) & 1) * 8;
#pragma unroll
            for (int nh = 0; nh < 2; nh++) {
                int rr = wn * 32 + nh * 16 + brow_;
                ldsm_x4(bh[nh * 2][0], bh[nh * 2][1], bh[nh * 2 + 1][0], bh[nh * 2 + 1][1],
                        &Wh_s[rr][bcol]);
                ldsm_x4(bl[nh * 2][0], bl[nh * 2][1], bl[nh * 2 + 1][0], bl[nh * 2 + 1][1],
                        &Wl_s[rr][bcol]);
            }
#pragma unroll
            for (int mf = 0; mf < 2; mf++)
#pragma unroll
                for (int nf = 0; nf < 4; nf++) {
                    mma_bf16(acc[mf][nf], ah[mf], bh[nf]);
                    mma_bf16(acc[mf][nf], ah[mf], bl[nf]);
                    mma_bf16(acc[mf][nf], al[mf], bh[nf]);
                }
        }
        __syncthreads();
    }

#pragma unroll
    for (int nf = 0; nf < 4; nf++) {
        int jc = j0 + wn * 32 + nf * 8 + (lane & 3) * 2;
        float b0 = __ldg(bv + jc), b1 = __ldg(bv + jc + 1);
        int ncol = n0 + wn * 32 + nf * 8 + (lane & 3) * 2;
#pragma unroll
        for (int mf = 0; mf < 2; mf++) {
            int r0 = m0 + wm * 32 + mf * 16 + (lane >> 2);
            float2 v0 = make_float2(acc[mf][nf][0] + b0, acc[mf][nf][1] + b1);
            float2 v1 = make_float2(acc[mf][nf][2] + b0, acc[mf][nf][3] + b1);
            *(float2*)(g_XP + (size_t)r0 * 1536 + ncol) = v0;
            *(float2*)(g_XP + (size_t)(r0 + 8) * 1536 + ncol) = v1;
        }
    }
}

// ============================================================================
// Persistent scan kernel, 512 threads (16 warps) per CTA for latency hiding.
// 128 CTAs = 32 column-groups (16 j each) x 4 batch-groups (8 b each).
// Wh slices resident in SMEM all 512 steps. Two release/acquire grid barriers
// per step, scoped to 32-CTA batch groups (counters padded to 128B).
// ============================================================================

__device__ __forceinline__ void bg_barrier(unsigned* ctr, unsigned target) {
    __syncthreads();
    if (threadIdx.x == 0) {
        unsigned old;
        asm volatile("atom.release.gpu.global.add.u32 %0, [%1], 1;"
                     : "=r"(old) : "l"(ctr) : "memory");
        unsigned v;
        do {
            asm volatile("ld.acquire.gpu.global.u32 %0, [%1];"
                         : "=r"(v) : "l"(ctr) : "memory");
        } while (v < target);
    }
    __syncthreads();
}

__device__ __forceinline__ float4 ldvol4(const float* p) {
    float4 v;
    asm volatile("ld.volatile.global.v4.f32 {%0,%1,%2,%3}, [%4];"
                 : "=f"(v.x), "=f"(v.y), "=f"(v.z), "=f"(v.w)
                 : "l"(p) : "memory");
    return v;
}

// SMEM layout (floats): Wu_s[16*512] @0, Wr_s @8192, Wo_s @16384,
// h_s[8][516] @24576, hr_s[8][516] @28704, red[4352] @32832, U_s[16*8] @37184
#define SCAN_SMEM_FLOATS 37312
#define SCAN_SMEM_BYTES  (SCAN_SMEM_FLOATS * 4)

__global__ __launch_bounds__(512, 1) void scan_kernel(
    int layer,
    const float* __restrict__ Wr_l, const float* __restrict__ Wu_l,
    const float* __restrict__ Wo_l,
    float* __restrict__ dout)
{
    extern __shared__ float sm[];
    float* h_s  = sm + 24576;   // [8][516]
    float* hr_s = sm + 28704;   // [8][516]
    float* red  = sm + 32832;   // phase1: 256x17; phase2: 128x33
    float* U_s  = sm + 37184;   // [16][8]: jl*8 + b

    int tid = threadIdx.x;
    int cg = blockIdx.x >> 2;   // 0..31 column group (j in [cg*16, cg*16+16))
    int bg = blockIdx.x & 3;    // 0..3  batch group  (b in [bg*8,  bg*8+8))
    unsigned* ctr = &g_bar[bg * 32];

    // Load recurrent-weight slices W_g[j][512:1024] -> SMEM (coalesced float4)
    {
        const float* srcs[3] = { Wu_l, Wr_l, Wo_l };
#pragma unroll
        for (int g = 0; g < 3; g++) {
            const float* src = srcs[g];
            float* dst = sm + g * 8192;
            for (int it = 0; it < 4; it++) {
                int word = (it * 512 + tid) * 4;
                int jl = word >> 9, k = word & 511;
                float4 v = *(const float4*)(src + (size_t)(cg * 16 + jl) * 1024 + 512 + k);
                *(float4*)(dst + jl * 512 + k) = v;
            }
        }
    }
    // zero own slice of h0
    if (tid < 128) {
        int b = tid >> 4, jl = tid & 15;
        g_hbuf[0][(bg * 8 + b) * 512 + cg * 16 + jl] = 0.f;
    }
    unsigned gen = 0;
    bg_barrier(ctr, (++gen) * 32);

    // Phase-1 mapping: 16 warps; warp w covers (j,gate)-cols {2w, 2w+1}
    //   (w<8 -> u gate, w>=8 -> r gate); lane: ks1=lane&15 (16-way split-K,
    //   stride-16), th=lane>>4 (b-tile of 4).
    // Phase-2 mapping: warp = (jt in [0,8), bt in {0,1}); covers j {2jt,2jt+1},
    //   b-tile bt*4; lane = ks2 (32-way split-K, stride-32).
    int w = tid >> 5, lane = tid & 31;
    int ks1 = lane & 15, th = lane >> 4;
    int jt2 = w >> 1, bt2 = w & 1, ks2 = lane;

    const float* Wp1 = (w < 8) ? (sm + (2 * w) * 512)
                               : (sm + 8192 + (2 * w - 16) * 512);
    const float* Wp2 = sm + 16384 + (jt2 * 2) * 512;

    int cur = 0;
    for (int t = 0; t < 512; t++) {
        // ---- prefetch XP values for this step (consumed after reductions) ----
        float xp1 = 0.f, xp2 = 0.f;
        if (tid < 256) {
            int jg = tid >> 3, b = tid & 7;
            size_t m = (size_t)t * 32 + bg * 8 + b;
            size_t col = (jg < 16) ? (size_t)(cg * 16 + jg)
                                   : (size_t)(512 + cg * 16 + jg - 16);
            xp1 = __ldg(&g_XP[m * 1536 + col]);
        }
        if (tid < 128) {
            int jl = tid >> 3, b = tid & 7;
            size_t m = (size_t)t * 32 + bg * 8 + b;
            xp2 = __ldg(&g_XP[m * 1536 + 1024 + cg * 16 + jl]);
        }

        // ---- stage h (own 8 batches, full 512 cols) into SMEM ----
#pragma unroll
        for (int q = 0; q < 2; q++) {
            int f = (q * 512 + tid) * 4;
            int bl = f >> 9, k = f & 511;
            float4 v = ldvol4(&g_hbuf[cur][(bg * 8 + bl) * 512 + k]);
            *(float4*)(h_s + bl * 516 + k) = v;
        }
        __syncthreads();

        // ---- phase 1: u and r gates (32 (j,g)-cols x 8 b per CTA) ----
        float acc[2][4];
#pragma unroll
        for (int a = 0; a < 2; a++)
#pragma unroll
            for (int b = 0; b < 4; b++) acc[a][b] = 0.f;
        {
            const float* hp = h_s + (th * 4) * 516;
#pragma unroll 4
            for (int i = 0; i < 32; i++) {
                int k = ks1 + 16 * i;
                float h0 = hp[k], h1 = hp[516 + k], h2 = hp[1032 + k], h3 = hp[1548 + k];
                float w0 = Wp1[k], w1 = Wp1[512 + k];
                acc[0][0] = fmaf(w0, h0, acc[0][0]);
                acc[0][1] = fmaf(w0, h1, acc[0][1]);
                acc[0][2] = fmaf(w0, h2, acc[0][2]);
                acc[0][3] = fmaf(w0, h3, acc[0][3]);
                acc[1][0] = fmaf(w1, h0, acc[1][0]);
                acc[1][1] = fmaf(w1, h1, acc[1][1]);
                acc[1][2] = fmaf(w1, h2, acc[1][2]);
                acc[1][3] = fmaf(w1, h3, acc[1][3]);
            }
        }
#pragma unroll
        for (int ji = 0; ji < 2; ji++)
#pragma unroll
            for (int bi = 0; bi < 4; bi++)
                red[((2 * w + ji) * 8 + th * 4 + bi) * 17 + ks1] = acc[ji][bi];
        __syncthreads();
        if (tid < 256) {
            int o = tid, jg = o >> 3, b = o & 7;
            float s = 0.f;
#pragma unroll
            for (int kk = 0; kk < 16; kk++) s += red[o * 17 + kk];
            if (jg < 16) {                      // update gate u
                float pre = s + xp1;
                U_s[jg * 8 + b] = 1.f / (1.f + expf(-pre));
            } else {                            // reset gate r -> publish h*r
                int j = cg * 16 + (jg - 16);
                float pre = s + xp1;
                float r = 1.f / (1.f + expf(-pre));
                g_hr[(bg * 8 + b) * 512 + j] = h_s[b * 516 + j] * r;
            }
        }
        bg_barrier(ctr, (++gen) * 32);

        // ---- phase 2: o gate + h update (16 j x 8 b per CTA) ----
#pragma unroll
        for (int q = 0; q < 2; q++) {
            int f = (q * 512 + tid) * 4;
            int bl = f >> 9, k = f & 511;
            float4 v = ldvol4(&g_hr[(bg * 8 + bl) * 512 + k]);
            *(float4*)(hr_s + bl * 516 + k) = v;
        }
        __syncthreads();
        float a2[2][4];
#pragma unroll
        for (int a = 0; a < 2; a++)
#pragma unroll
            for (int b = 0; b < 4; b++) a2[a][b] = 0.f;
        {
            const float* hp = hr_s + (bt2 * 4) * 516;
#pragma unroll 4
            for (int i = 0; i < 16; i++) {
                int k = ks2 + 32 * i;
                float h0 = hp[k], h1 = hp[516 + k], h2 = hp[1032 + k], h3 = hp[1548 + k];
                float w0 = Wp2[k], w1 = Wp2[512 + k];
                a2[0][0] = fmaf(w0, h0, a2[0][0]);
                a2[0][1] = fmaf(w0, h1, a2[0][1]);
                a2[0][2] = fmaf(w0, h2, a2[0][2]);
                a2[0][3] = fmaf(w0, h3, a2[0][3]);
                a2[1][0] = fmaf(w1, h0, a2[1][0]);
                a2[1][1] = fmaf(w1, h1, a2[1][1]);
                a2[1][2] = fmaf(w1, h2, a2[1][2]);
                a2[1][3] = fmaf(w1, h3, a2[1][3]);
            }
        }
#pragma unroll
        for (int ji = 0; ji < 2; ji++)
#pragma unroll
            for (int bi = 0; bi < 4; bi++)
                red[((jt2 * 2 + ji) * 8 + bt2 * 4 + bi) * 33 + ks2] = a2[ji][bi];
        __syncthreads();
        if (tid < 128) {
            int o = tid, jl = o >> 3, b = o & 7;
            float s = 0.f;
#pragma unroll
            for (int kk = 0; kk < 32; kk++) s += red[o * 33 + kk];
            int j = cg * 16 + jl;
            int bglob = bg * 8 + b;
            size_t m = (size_t)t * 32 + bglob;
            float pre = s + xp2;
            float ov = tanhf(pre);
            float u = U_s[jl * 8 + b];
            float hold = h_s[b * 516 + j];
            float hn = fmaf(u, ov - hold, hold);      // h*(1-u) + o*u
            g_hbuf[cur ^ 1][bglob * 512 + j] = hn;
            if (layer == 0) g_Hseq[m * 512 + j] = hn;
            if (t == 511) dout[layer * 16384 + bglob * 512 + j] = hn;
        }
        bg_barrier(ctr, (++gen) * 32);
        cur ^= 1;
    }
}

// ============================================================================
extern "C" void kernel_launch(void* const* d_in, const int* in_sizes, int n_in,
                              void* d_out, int out_size)
{
    (void)in_sizes; (void)n_in; (void)out_size;
    const float* x  = (const float*)d_in[0];
    const float* Wr = (const float*)d_in[1];
    const float* br = (const float*)d_in[2];
    const float* Wu = (const float*)d_in[3];
    const float* bu = (const float*)d_in[4];
    const float* Wo = (const float*)d_in[5];
    const float* bo = (const float*)d_in[6];
    float* out = (float*)d_out;

    cudaFuncSetAttribute(scan_kernel,
                         cudaFuncAttributeMaxDynamicSharedMemorySize,
                         SCAN_SMEM_BYTES);

    for (int l = 0; l < 2; l++) {
        size_t woff = (size_t)l * 512 * 1024;
        reset_kernel<<<1, 128>>>();
        convA_kernel<<<8192, 256>>>(x, l);
        convW_kernel<<<768, 256>>>(Wr + woff, Wu + woff, Wo + woff);
        xproj_mma_kernel<<<dim3(128, 24), 256>>>(br + l * 512, bu + l * 512, bo + l * 512);
        scan_kernel<<<128, 512, SCAN_SMEM_BYTES>>>(l,
                                                   Wr + woff, Wu + woff, Wo + woff,
                                                   out);
    }
}

// round 11
// speedup vs baseline: 1.3822x; 1.3822x over previous
#include <cuda_runtime.h>
#include <cuda_bf16.h>
#include <math.h>

// Problem constants: B=32, T=512, D=H=512, L=2
// Inputs (metadata order): x, Wr, br, Wu, bu, Wo, bo
// Output: (L, B, H) float32 = 32768 elements.

#define T_LEN 512
#define BATCH 32
#define HID   512

// ---------------- device scratch (no cudaMalloc allowed) ----------------
__device__ float    g_XP[(size_t)16384 * 1536];   // x-projections [m=t*32+b][n=g*512+j], g:0=u,1=r,2=o
__device__ float    g_Hseq[(size_t)16384 * 512];  // layer-0 hidden sequence [m=t*32+b][j]
__device__ float    g_hbuf[2][BATCH * HID];       // ping-pong h, [b][j]
__device__ float    g_hr[BATCH * HID];            // h*r exchange, [b][j]
__device__ unsigned g_bar[4 * 32];                // per-batch-group barriers, 128B apart

// bf16-split scratch for tensor-core xproj
__device__ __nv_bfloat16 g_Ah[(size_t)16384 * 512];
__device__ __nv_bfloat16 g_Al[(size_t)16384 * 512];
__device__ __nv_bfloat16 g_Wh[(size_t)3 * 512 * 512];
__device__ __nv_bfloat16 g_Wl[(size_t)3 * 512 * 512];

__global__ void reset_kernel() {
    if (threadIdx.x < 128) g_bar[threadIdx.x] = 0u;
}

// ============================================================================
// fp32 -> (bf16 hi, bf16 lo) split helpers
// ============================================================================
__device__ __forceinline__ void split_bf16(float v, __nv_bfloat16& hi, __nv_bfloat16& lo) {
    hi = __float2bfloat16(v);
    lo = __float2bfloat16(v - __bfloat162float(hi));
}

// pack two fp32 (k, k+1) into bf16x2 hi and lo fragments (low half = first elem)
__device__ __forceinline__ void pack_split(float x0, float x1, unsigned& hi, unsigned& lo) {
    __nv_bfloat16 h0, h1, l0, l1;
    split_bf16(x0, h0, l0);
    split_bf16(x1, h1, l1);
    hi = ((unsigned)__bfloat16_as_ushort(h1) << 16) | (unsigned)__bfloat16_as_ushort(h0);
    lo = ((unsigned)__bfloat16_as_ushort(l1) << 16) | (unsigned)__bfloat16_as_ushort(l0);
}

// A matrix: 16384 x 512.  amode 0: from x[b][t][k] (m = t*32+b). amode 1: from g_Hseq (row-major).
__global__ __launch_bounds__(256) void convA_kernel(const float* __restrict__ x, int amode) {
    size_t idx = ((size_t)blockIdx.x * 256 + threadIdx.x) * 4;
    int m = (int)(idx >> 9);
    int k = (int)(idx & 511);
    const float* src = amode ? (g_Hseq + idx)
                             : (x + ((size_t)(m & 31) * 512 + (m >> 5)) * 512 + k);
    float4 v = *(const float4*)src;
    __nv_bfloat16 h0, h1, h2, h3, l0, l1, l2, l3;
    split_bf16(v.x, h0, l0); split_bf16(v.y, h1, l1);
    split_bf16(v.z, h2, l2); split_bf16(v.w, h3, l3);
    ((__nv_bfloat162*)(g_Ah + idx))[0] = __nv_bfloat162(h0, h1);
    ((__nv_bfloat162*)(g_Ah + idx))[1] = __nv_bfloat162(h2, h3);
    ((__nv_bfloat162*)(g_Al + idx))[0] = __nv_bfloat162(l0, l1);
    ((__nv_bfloat162*)(g_Al + idx))[1] = __nv_bfloat162(l2, l3);
}

// W x-halves: g (0=u,1=r,2=o) x 512 j x 512 k  (source row stride 1024)
__global__ __launch_bounds__(256) void convW_kernel(
    const float* __restrict__ Wr, const float* __restrict__ Wu, const float* __restrict__ Wo) {
    size_t idx = ((size_t)blockIdx.x * 256 + threadIdx.x) * 4;   // over 3*512*512
    int g = (int)(idx >> 18);
    int r = (int)(idx & 262143);
    int j = r >> 9, k = r & 511;
    const float* W = (g == 0) ? Wu : (g == 1) ? Wr : Wo;
    float4 v = *(const float4*)(W + (size_t)j * 1024 + k);
    __nv_bfloat16 h0, h1, h2, h3, l0, l1, l2, l3;
    split_bf16(v.x, h0, l0); split_bf16(v.y, h1, l1);
    split_bf16(v.z, h2, l2); split_bf16(v.w, h3, l3);
    ((__nv_bfloat162*)(g_Wh + idx))[0] = __nv_bfloat162(h0, h1);
    ((__nv_bfloat162*)(g_Wh + idx))[1] = __nv_bfloat162(h2, h3);
    ((__nv_bfloat162*)(g_Wl + idx))[0] = __nv_bfloat162(l0, l1);
    ((__nv_bfloat162*)(g_Wl + idx))[1] = __nv_bfloat162(l2, l3);
}

// ============================================================================
// mma.sync m16n8k16 bf16 helper (row.col, fp32 accum)
// ============================================================================
__device__ __forceinline__ void mma_bf16(float* c, const unsigned* a, const unsigned* b) {
    asm volatile("mma.sync.aligned.m16n8k16.row.col.f32.bf16.bf16.f32 "
                 "{%0,%1,%2,%3}, {%4,%5,%6,%7}, {%8,%9}, {%0,%1,%2,%3};"
                 : "+f"(c[0]), "+f"(c[1]), "+f"(c[2]), "+f"(c[3])
                 : "r"(a[0]), "r"(a[1]), "r"(a[2]), "r"(a[3]), "r"(b[0]), "r"(b[1]));
}

__device__ __forceinline__ void ldsm_x4(unsigned& r0, unsigned& r1, unsigned& r2, unsigned& r3,
                                        const __nv_bfloat16* p) {
    unsigned a = (unsigned)__cvta_generic_to_shared(p);
    asm volatile("ldmatrix.sync.aligned.m8n8.x4.shared.b16 {%0,%1,%2,%3}, [%4];"
                 : "=r"(r0), "=r"(r1), "=r"(r2), "=r"(r3) : "r"(a));
}

// ============================================================================
// Tensor-core xproj:  g_XP[m][n] = A[m][:] . W[n][:] + b[n]   (unchanged, 266us)
// ============================================================================
#define SM_PITCH 40

__global__ __launch_bounds__(256) void xproj_mma_kernel(
    const float* __restrict__ br, const float* __restrict__ bu, const float* __restrict__ bo) {
    __shared__ __nv_bfloat16 Ah_s[128][SM_PITCH];
    __shared__ __nv_bfloat16 Al_s[128][SM_PITCH];
    __shared__ __nv_bfloat16 Wh_s[64][SM_PITCH];
    __shared__ __nv_bfloat16 Wl_s[64][SM_PITCH];

    int tid = threadIdx.x;
    int m0 = blockIdx.x * 128;
    int n0 = blockIdx.y * 64;
    int g = n0 >> 9, j0 = n0 & 511;
    const float* bv = (g == 0) ? bu : (g == 1) ? br : bo;

    int w = tid >> 5, lane = tid & 31;
    int wm = w >> 1, wn = w & 1;

    float acc[2][4][4];
#pragma unroll
    for (int mf = 0; mf < 2; mf++)
#pragma unroll
        for (int nf = 0; nf < 4; nf++)
#pragma unroll
            for (int i = 0; i < 4; i++) acc[mf][nf][i] = 0.f;

    for (int k0 = 0; k0 < 512; k0 += 32) {
#pragma unroll
        for (int q = 0; q < 2; q++) {
            int u = q * 256 + tid;
            int row = u >> 2, c8 = (u & 3) * 8;
            size_t go = (size_t)(m0 + row) * 512 + k0 + c8;
            *(uint4*)&Ah_s[row][c8] = *(const uint4*)(g_Ah + go);
            *(uint4*)&Al_s[row][c8] = *(const uint4*)(g_Al + go);
        }
        {
            int row = tid >> 2, c8 = (tid & 3) * 8;
            size_t go = ((size_t)g * 512 + j0 + row) * 512 + k0 + c8;
            *(uint4*)&Wh_s[row][c8] = *(const uint4*)(g_Wh + go);
            *(uint4*)&Wl_s[row][c8] = *(const uint4*)(g_Wl + go);
        }
        __syncthreads();

#pragma unroll
        for (int k16 = 0; k16 < 32; k16 += 16) {
            unsigned ah[2][4], al[2][4], bh[4][2], bl[4][2];
            int arow = wm * 32 + (lane & 15);
            int acol = k16 + (lane >> 4) * 8;
#pragma unroll
            for (int mf = 0; mf < 2; mf++) {
                ldsm_x4(ah[mf][0], ah[mf][1], ah[mf][2], ah[mf][3], &Ah_s[arow + mf * 16][acol]);
                ldsm_x4(al[mf][0], al[mf][1], al[mf][2], al[mf][3], &Al_s[arow + mf * 16][acol]);
            }
            int brow_ = ((lane & 16) >> 1) + (lane & 7);
            int bcol = k16 + ((lane >> 3) & 1) * 8;
#pragma unroll
            for (int nh = 0; nh < 2; nh++) {
                int rr = wn * 32 + nh * 16 + brow_;
                ldsm_x4(bh[nh * 2][0], bh[nh * 2][1], bh[nh * 2 + 1][0], bh[nh * 2 + 1][1],
                        &Wh_s[rr][bcol]);
                ldsm_x4(bl[nh * 2][0], bl[nh * 2][1], bl[nh * 2 + 1][0], bl[nh * 2 + 1][1],
                        &Wl_s[rr][bcol]);
            }
#pragma unroll
            for (int mf = 0; mf < 2; mf++)
#pragma unroll
                for (int nf = 0; nf < 4; nf++) {
                    mma_bf16(acc[mf][nf], ah[mf], bh[nf]);
                    mma_bf16(acc[mf][nf], ah[mf], bl[nf]);
                    mma_bf16(acc[mf][nf], al[mf], bh[nf]);
                }
        }
        __syncthreads();
    }

#pragma unroll
    for (int nf = 0; nf < 4; nf++) {
        int jc = j0 + wn * 32 + nf * 8 + (lane & 3) * 2;
        float b0 = __ldg(bv + jc), b1 = __ldg(bv + jc + 1);
        int ncol = n0 + wn * 32 + nf * 8 + (lane & 3) * 2;
#pragma unroll
        for (int mf = 0; mf < 2; mf++) {
            int r0 = m0 + wm * 32 + mf * 16 + (lane >> 2);
            float2 v0 = make_float2(acc[mf][nf][0] + b0, acc[mf][nf][1] + b1);
            float2 v1 = make_float2(acc[mf][nf][2] + b0, acc[mf][nf][3] + b1);
            *(float2*)(g_XP + (size_t)r0 * 1536 + ncol) = v0;
            *(float2*)(g_XP + (size_t)(r0 + 8) * 1536 + ncol) = v1;
        }
    }
}

// ============================================================================
// Persistent scan kernel — tensor-core matvecs with register-resident weight
// fragments (bf16-split). 128 CTAs = 32 column-groups (16 j) x 4 batch-groups
// (8 b). 512 threads = 16 warps, each owning a 32-wide k-slice.
// Two release/acquire grid barriers per step, scoped to 32-CTA batch groups.
// ============================================================================

__device__ __forceinline__ void bg_barrier(unsigned* ctr, unsigned target) {
    __syncthreads();
    if (threadIdx.x == 0) {
        unsigned old;
        asm volatile("atom.release.gpu.global.add.u32 %0, [%1], 1;"
                     : "=r"(old) : "l"(ctr) : "memory");
        unsigned v;
        do {
            asm volatile("ld.acquire.gpu.global.u32 %0, [%1];"
                         : "=r"(v) : "l"(ctr) : "memory");
        } while (v < target);
    }
    __syncthreads();
}

__device__ __forceinline__ float4 ldvol4(const float* p) {
    float4 v;
    asm volatile("ld.volatile.global.v4.f32 {%0,%1,%2,%3}, [%4];"
                 : "=f"(v.x), "=f"(v.y), "=f"(v.z), "=f"(v.w)
                 : "l"(p) : "memory");
    return v;
}

// SMEM (floats): h_s[8][520] @0, hr_s[8][520] @4160, red[4096] @8320, U_s[128] @12416
#define H_PITCH 520
#define SCAN_SMEM_FLOATS 12544
#define SCAN_SMEM_BYTES  (SCAN_SMEM_FLOATS * 4)

__global__ __launch_bounds__(512, 1) void scan_kernel(
    int layer,
    const float* __restrict__ Wr_l, const float* __restrict__ Wu_l,
    const float* __restrict__ Wo_l,
    float* __restrict__ dout)
{
    extern __shared__ float sm[];
    float* h_s  = sm;            // [8][520]
    float* hr_s = sm + 4160;     // [8][520]
    float* red  = sm + 8320;     // phase1: 16 warps x 256; phase2: 16 x 128
    float* U_s  = sm + 12416;    // [16][8]

    int tid = threadIdx.x;
    int cg = blockIdx.x >> 2;    // column group: j in [cg*16, cg*16+16)
    int bg = blockIdx.x & 3;     // batch group:  b in [bg*8,  bg*8+8)
    unsigned* ctr = &g_bar[bg * 32];

    int w = tid >> 5, lane = tid & 31;
    int q = lane & 3;            // frag quad index
    int r = lane >> 2;           // frag row / batch index
    int k0 = 32 * w;             // this warp's k-slice (recurrent half)

    // ---- load step-invariant weight fragments into registers (bf16-split) ----
    // Phase-1 A frags: mt=0 -> Wu (rows jg 0..15), mt=1 -> Wr (rows jg 16..31)
    unsigned a1h[2][2][4], a1l[2][2][4];   // [mt][ks][i]
#pragma unroll
    for (int mt = 0; mt < 2; mt++) {
        const float* Wg = mt ? Wr_l : Wu_l;
#pragma unroll
        for (int ks = 0; ks < 2; ks++)
#pragma unroll
            for (int i = 0; i < 4; i++) {
                int row = cg * 16 + r + 8 * (i & 1);
                int col = 512 + k0 + 16 * ks + 2 * q + 8 * (i >> 1);
                float2 v = *(const float2*)(Wg + (size_t)row * 1024 + col);
                pack_split(v.x, v.y, a1h[mt][ks][i], a1l[mt][ks][i]);
            }
    }
    // Phase-2 A frags: Wo
    unsigned a2h[2][4], a2l[2][4];
#pragma unroll
    for (int ks = 0; ks < 2; ks++)
#pragma unroll
        for (int i = 0; i < 4; i++) {
            int row = cg * 16 + r + 8 * (i & 1);
            int col = 512 + k0 + 16 * ks + 2 * q + 8 * (i >> 1);
            float2 v = *(const float2*)(Wo_l + (size_t)row * 1024 + col);
            pack_split(v.x, v.y, a2h[ks][i], a2l[ks][i]);
        }

    // zero own slice of h0
    if (tid < 128) {
        int b = tid >> 4, jl = tid & 15;
        g_hbuf[0][(bg * 8 + b) * 512 + cg * 16 + jl] = 0.f;
    }
    unsigned gen = 0;
    bg_barrier(ctr, (++gen) * 32);

    int cur = 0;
    for (int t = 0; t < 512; t++) {
        // ---- prefetch XP for this step (consumed after reductions) ----
        float xp1 = 0.f, xp2 = 0.f;
        if (tid < 256) {
            int jg = tid >> 3, b = tid & 7;
            size_t m = (size_t)t * 32 + bg * 8 + b;
            size_t col = (jg < 16) ? (size_t)(cg * 16 + jg)
                                   : (size_t)(512 + cg * 16 + jg - 16);
            xp1 = __ldg(&g_XP[m * 1536 + col]);
        }
        if (tid < 128) {
            int jl = tid >> 3, b = tid & 7;
            size_t m = (size_t)t * 32 + bg * 8 + b;
            xp2 = __ldg(&g_XP[m * 1536 + 1024 + cg * 16 + jl]);
        }

        // ---- stage h (own 8 batches, 512 cols) into SMEM ----
#pragma unroll
        for (int qq = 0; qq < 2; qq++) {
            int f = (qq * 512 + tid) * 4;
            int bl = f >> 9, k = f & 511;
            float4 v = ldvol4(&g_hbuf[cur][(bg * 8 + bl) * 512 + k]);
            *(float4*)(h_s + bl * H_PITCH + k) = v;
        }
        __syncthreads();

        // ---- phase 1: C[32 jg][8 b] = W_{u,r} . h  (tensor cores, split-K 16) ----
        float c1[2][4];
#pragma unroll
        for (int mt = 0; mt < 2; mt++)
#pragma unroll
            for (int i = 0; i < 4; i++) c1[mt][i] = 0.f;
#pragma unroll
        for (int ks = 0; ks < 2; ks++) {
            int kb = k0 + 16 * ks + 2 * q;
            float2 v0 = *(const float2*)(h_s + r * H_PITCH + kb);
            float2 v1 = *(const float2*)(h_s + r * H_PITCH + kb + 8);
            unsigned bh[2], bl_[2];
            pack_split(v0.x, v0.y, bh[0], bl_[0]);
            pack_split(v1.x, v1.y, bh[1], bl_[1]);
#pragma unroll
            for (int mt = 0; mt < 2; mt++) {
                mma_bf16(c1[mt], a1h[mt][ks], bh);
                mma_bf16(c1[mt], a1h[mt][ks], bl_);
                mma_bf16(c1[mt], a1l[mt][ks], bh);
            }
        }
        // write partials: red[w*256 + jg*8 + n]
#pragma unroll
        for (int mt = 0; mt < 2; mt++) {
            float* rp = red + w * 256 + (mt * 16 + r) * 8 + 2 * q;
            *(float2*)rp = make_float2(c1[mt][0], c1[mt][1]);
            *(float2*)(rp + 64) = make_float2(c1[mt][2], c1[mt][3]);   // rows +8
        }
        __syncthreads();
        if (tid < 256) {
            int jg = tid >> 3, b = tid & 7;
            float s = 0.f;
#pragma unroll
            for (int ww = 0; ww < 16; ww++) s += red[ww * 256 + tid];
            if (jg < 16) {                      // update gate u
                float pre = s + xp1;
                U_s[jg * 8 + b] = 1.f / (1.f + expf(-pre));
            } else {                            // reset gate r -> publish h*r
                int j = cg * 16 + (jg - 16);
                float pre = s + xp1;
                float rr = 1.f / (1.f + expf(-pre));
                g_hr[(bg * 8 + b) * 512 + j] = h_s[b * H_PITCH + j] * rr;
            }
        }
        bg_barrier(ctr, (++gen) * 32);

        // ---- stage h*r ----
#pragma unroll
        for (int qq = 0; qq < 2; qq++) {
            int f = (qq * 512 + tid) * 4;
            int bl = f >> 9, k = f & 511;
            float4 v = ldvol4(&g_hr[(bg * 8 + bl) * 512 + k]);
            *(float4*)(hr_s + bl * H_PITCH + k) = v;
        }
        __syncthreads();

        // ---- phase 2: C[16 j][8 b] = Wo . (h*r) ----
        float c2[4];
#pragma unroll
        for (int i = 0; i < 4; i++) c2[i] = 0.f;
#pragma unroll
        for (int ks = 0; ks < 2; ks++) {
            int kb = k0 + 16 * ks + 2 * q;
            float2 v0 = *(const float2*)(hr_s + r * H_PITCH + kb);
            float2 v1 = *(const float2*)(hr_s + r * H_PITCH + kb + 8);
            unsigned bh[2], bl_[2];
            pack_split(v0.x, v0.y, bh[0], bl_[0]);
            pack_split(v1.x, v1.y, bh[1], bl_[1]);
            mma_bf16(c2, a2h[ks], bh);
            mma_bf16(c2, a2h[ks], bl_);
            mma_bf16(c2, a2l[ks], bh);
        }
        {
            float* rp = red + w * 128 + r * 8 + 2 * q;
            *(float2*)rp = make_float2(c2[0], c2[1]);
            *(float2*)(rp + 64) = make_float2(c2[2], c2[3]);
        }
        __syncthreads();
        if (tid < 128) {
            int jl = tid >> 3, b = tid & 7;
            float s = 0.f;
#pragma unroll
            for (int ww = 0; ww < 16; ww++) s += red[ww * 128 + tid];
            int j = cg * 16 + jl;
            int bglob = bg * 8 + b;
            size_t m = (size_t)t * 32 + bglob;
            float pre = s + xp2;
            float ov = tanhf(pre);
            float u = U_s[jl * 8 + b];
            float hold = h_s[b * H_PITCH + j];
            float hn = fmaf(u, ov - hold, hold);      // h*(1-u) + o*u
            g_hbuf[cur ^ 1][bglob * 512 + j] = hn;
            if (layer == 0) g_Hseq[m * 512 + j] = hn;
            if (t == 511) dout[layer * 16384 + bglob * 512 + j] = hn;
        }
        bg_barrier(ctr, (++gen) * 32);
        cur ^= 1;
    }
}

// ============================================================================
extern "C" void kernel_launch(void* const* d_in, const int* in_sizes, int n_in,
                              void* d_out, int out_size)
{
    (void)in_sizes; (void)n_in; (void)out_size;
    const float* x  = (const float*)d_in[0];
    const float* Wr = (const float*)d_in[1];
    const float* br = (const float*)d_in[2];
    const float* Wu = (const float*)d_in[3];
    const float* bu = (const float*)d_in[4];
    const float* Wo = (const float*)d_in[5];
    const float* bo = (const float*)d_in[6];
    float* out = (float*)d_out;

    cudaFuncSetAttribute(scan_kernel,
                         cudaFuncAttributeMaxDynamicSharedMemorySize,
                         SCAN_SMEM_BYTES);

    for (int l = 0; l < 2; l++) {
        size_t woff = (size_t)l * 512 * 1024;
        reset_kernel<<<1, 128>>>();
        convA_kernel<<<8192, 256>>>(x, l);
        convW_kernel<<<768, 256>>>(Wr + woff, Wu + woff, Wo + woff);
        xproj_mma_kernel<<<dim3(128, 24), 256>>>(br + l * 512, bu + l * 512, bo + l * 512);
        scan_kernel<<<128, 512, SCAN_SMEM_BYTES>>>(l,
                                                   Wr + woff, Wu + woff, Wo + woff,
                                                   out);
    }
}

// round 12
// speedup vs baseline: 1.4403x; 1.0421x over previous
#include <cuda_runtime.h>
#include <cuda_bf16.h>
#include <math.h>

// Problem constants: B=32, T=512, D=H=512, L=2
// Inputs (metadata order): x, Wr, br, Wu, bu, Wo, bo
// Output: (L, B, H) float32 = 32768 elements.

// ---------------- device scratch (no cudaMalloc allowed) ----------------
__device__ float    g_XP[(size_t)16384 * 1536];   // x-projections [m=t*32+b][n=g*512+j], g:0=u,1=r,2=o
__device__ float    g_Hseq[(size_t)16384 * 512];  // layer-0 hidden sequence [m=t*32+b][j]
__device__ float    g_hbuf[2][32 * 512];          // ping-pong h, [b][j]
__device__ float    g_hr[32 * 512];               // h*r exchange, [b][j]
__device__ unsigned g_bar[4 * 32];                // per-batch-group barriers, 128B apart

// bf16-split scratch for tensor-core xproj
__device__ __nv_bfloat16 g_Ah[(size_t)16384 * 512];
__device__ __nv_bfloat16 g_Al[(size_t)16384 * 512];
__device__ __nv_bfloat16 g_Wh[(size_t)3 * 512 * 512];
__device__ __nv_bfloat16 g_Wl[(size_t)3 * 512 * 512];

// ============================================================================
// fp32 -> (bf16 hi, bf16 lo) split helpers
// ============================================================================
__device__ __forceinline__ void split_bf16(float v, __nv_bfloat16& hi, __nv_bfloat16& lo) {
    hi = __float2bfloat16(v);
    lo = __float2bfloat16(v - __bfloat162float(hi));
}

__device__ __forceinline__ void pack_split(float x0, float x1, unsigned& hi, unsigned& lo) {
    __nv_bfloat16 h0, h1, l0, l1;
    split_bf16(x0, h0, l0);
    split_bf16(x1, h1, l1);
    hi = ((unsigned)__bfloat16_as_ushort(h1) << 16) | (unsigned)__bfloat16_as_ushort(h0);
    lo = ((unsigned)__bfloat16_as_ushort(l1) << 16) | (unsigned)__bfloat16_as_ushort(l0);
}

// A matrix: 16384 x 512.  amode 0: from x[b][t][k] (m = t*32+b). amode 1: from g_Hseq.
// Block 0 also resets the scan barrier counters (stream-ordered, replay-safe).
__global__ __launch_bounds__(256) void convA_kernel(const float* __restrict__ x, int amode) {
    if (blockIdx.x == 0 && threadIdx.x < 128) g_bar[threadIdx.x] = 0u;
    size_t idx = ((size_t)blockIdx.x * 256 + threadIdx.x) * 4;
    int m = (int)(idx >> 9);
    int k = (int)(idx & 511);
    const float* src = amode ? (g_Hseq + idx)
                             : (x + ((size_t)(m & 31) * 512 + (m >> 5)) * 512 + k);
    float4 v = *(const float4*)src;
    __nv_bfloat16 h0, h1, h2, h3, l0, l1, l2, l3;
    split_bf16(v.x, h0, l0); split_bf16(v.y, h1, l1);
    split_bf16(v.z, h2, l2); split_bf16(v.w, h3, l3);
    ((__nv_bfloat162*)(g_Ah + idx))[0] = __nv_bfloat162(h0, h1);
    ((__nv_bfloat162*)(g_Ah + idx))[1] = __nv_bfloat162(h2, h3);
    ((__nv_bfloat162*)(g_Al + idx))[0] = __nv_bfloat162(l0, l1);
    ((__nv_bfloat162*)(g_Al + idx))[1] = __nv_bfloat162(l2, l3);
}

// W x-halves: g (0=u,1=r,2=o) x 512 j x 512 k  (source row stride 1024)
__global__ __launch_bounds__(256) void convW_kernel(
    const float* __restrict__ Wr, const float* __restrict__ Wu, const float* __restrict__ Wo) {
    size_t idx = ((size_t)blockIdx.x * 256 + threadIdx.x) * 4;   // over 3*512*512
    int g = (int)(idx >> 18);
    int r = (int)(idx & 262143);
    int j = r >> 9, k = r & 511;
    const float* W = (g == 0) ? Wu : (g == 1) ? Wr : Wo;
    float4 v = *(const float4*)(W + (size_t)j * 1024 + k);
    __nv_bfloat16 h0, h1, h2, h3, l0, l1, l2, l3;
    split_bf16(v.x, h0, l0); split_bf16(v.y, h1, l1);
    split_bf16(v.z, h2, l2); split_bf16(v.w, h3, l3);
    ((__nv_bfloat162*)(g_Wh + idx))[0] = __nv_bfloat162(h0, h1);
    ((__nv_bfloat162*)(g_Wh + idx))[1] = __nv_bfloat162(h2, h3);
    ((__nv_bfloat162*)(g_Wl + idx))[0] = __nv_bfloat162(l0, l1);
    ((__nv_bfloat162*)(g_Wl + idx))[1] = __nv_bfloat162(l2, l3);
}

// ============================================================================
// mma.sync m16n8k16 bf16 (row.col, fp32 accum) + ldmatrix
// ============================================================================
__device__ __forceinline__ void mma_bf16(float* c, const unsigned* a, const unsigned* b) {
    asm volatile("mma.sync.aligned.m16n8k16.row.col.f32.bf16.bf16.f32 "
                 "{%0,%1,%2,%3}, {%4,%5,%6,%7}, {%8,%9}, {%0,%1,%2,%3};"
                 : "+f"(c[0]), "+f"(c[1]), "+f"(c[2]), "+f"(c[3])
                 : "r"(a[0]), "r"(a[1]), "r"(a[2]), "r"(a[3]), "r"(b[0]), "r"(b[1]));
}

__device__ __forceinline__ void ldsm_x4(unsigned& r0, unsigned& r1, unsigned& r2, unsigned& r3,
                                        const __nv_bfloat16* p) {
    unsigned a = (unsigned)__cvta_generic_to_shared(p);
    asm volatile("ldmatrix.sync.aligned.m8n8.x4.shared.b16 {%0,%1,%2,%3}, [%4];"
                 : "=r"(r0), "=r"(r1), "=r"(r2), "=r"(r3) : "r"(a));
}

// ============================================================================
// Tensor-core xproj:  g_XP[m][n] = A[m][:] . W[n][:] + b[n]   (unchanged, ~265us)
// ============================================================================
#define SM_PITCH 40

__global__ __launch_bounds__(256) void xproj_mma_kernel(
    const float* __restrict__ br, const float* __restrict__ bu, const float* __restrict__ bo) {
    __shared__ __nv_bfloat16 Ah_s[128][SM_PITCH];
    __shared__ __nv_bfloat16 Al_s[128][SM_PITCH];
    __shared__ __nv_bfloat16 Wh_s[64][SM_PITCH];
    __shared__ __nv_bfloat16 Wl_s[64][SM_PITCH];

    int tid = threadIdx.x;
    int m0 = blockIdx.x * 128;
    int n0 = blockIdx.y * 64;
    int g = n0 >> 9, j0 = n0 & 511;
    const float* bv = (g == 0) ? bu : (g == 1) ? br : bo;

    int w = tid >> 5, lane = tid & 31;
    int wm = w >> 1, wn = w & 1;

    float acc[2][4][4];
#pragma unroll
    for (int mf = 0; mf < 2; mf++)
#pragma unroll
        for (int nf = 0; nf < 4; nf++)
#pragma unroll
            for (int i = 0; i < 4; i++) acc[mf][nf][i] = 0.f;

    for (int k0 = 0; k0 < 512; k0 += 32) {
#pragma unroll
        for (int q = 0; q < 2; q++) {
            int u = q * 256 + tid;
            int row = u >> 2, c8 = (u & 3) * 8;
            size_t go = (size_t)(m0 + row) * 512 + k0 + c8;
            *(uint4*)&Ah_s[row][c8] = *(const uint4*)(g_Ah + go);
            *(uint4*)&Al_s[row][c8] = *(const uint4*)(g_Al + go);
        }
        {
            int row = tid >> 2, c8 = (tid & 3) * 8;
            size_t go = ((size_t)g * 512 + j0 + row) * 512 + k0 + c8;
            *(uint4*)&Wh_s[row][c8] = *(const uint4*)(g_Wh + go);
            *(uint4*)&Wl_s[row][c8] = *(const uint4*)(g_Wl + go);
        }
        __syncthreads();

#pragma unroll
        for (int k16 = 0; k16 < 32; k16 += 16) {
            unsigned ah[2][4], al[2][4], bh[4][2], bl[4][2];
            int arow = wm * 32 + (lane & 15);
            int acol = k16 + (lane >> 4) * 8;
#pragma unroll
            for (int mf = 0; mf < 2; mf++) {
                ldsm_x4(ah[mf][0], ah[mf][1], ah[mf][2], ah[mf][3], &Ah_s[arow + mf * 16][acol]);
                ldsm_x4(al[mf][0], al[mf][1], al[mf][2], al[mf][3], &Al_s[arow + mf * 16][acol]);
            }
            int brow_ = ((lane & 16) >> 1) + (lane & 7);
            int bcol = k16 + ((lane >> 3) & 1) * 8;
#pragma unroll
            for (int nh = 0; nh < 2; nh++) {
                int rr = wn * 32 + nh * 16 + brow_;
                ldsm_x4(bh[nh * 2][0], bh[nh * 2][1], bh[nh * 2 + 1][0], bh[nh * 2 + 1][1],
                        &Wh_s[rr][bcol]);
                ldsm_x4(bl[nh * 2][0], bl[nh * 2][1], bl[nh * 2 + 1][0], bl[nh * 2 + 1][1],
                        &Wl_s[rr][bcol]);
            }
#pragma unroll
            for (int mf = 0; mf < 2; mf++)
#pragma unroll
                for (int nf = 0; nf < 4; nf++) {
                    mma_bf16(acc[mf][nf], ah[mf], bh[nf]);
                    mma_bf16(acc[mf][nf], ah[mf], bl[nf]);
                    mma_bf16(acc[mf][nf], al[mf], bh[nf]);
                }
        }
        __syncthreads();
    }

#pragma unroll
    for (int nf = 0; nf < 4; nf++) {
        int jc = j0 + wn * 32 + nf * 8 + (lane & 3) * 2;
        float b0 = __ldg(bv + jc), b1 = __ldg(bv + jc + 1);
        int ncol = n0 + wn * 32 + nf * 8 + (lane & 3) * 2;
#pragma unroll
        for (int mf = 0; mf < 2; mf++) {
            int r0 = m0 + wm * 32 + mf * 16 + (lane >> 2);
            float2 v0 = make_float2(acc[mf][nf][0] + b0, acc[mf][nf][1] + b1);
            float2 v1 = make_float2(acc[mf][nf][2] + b0, acc[mf][nf][3] + b1);
            *(float2*)(g_XP + (size_t)r0 * 1536 + ncol) = v0;
            *(float2*)(g_XP + (size_t)(r0 + 8) * 1536 + ncol) = v1;
        }
    }
}

// ============================================================================
// Persistent scan kernel — tensor-core matvecs, register weight fragments,
// NO SMEM staging: MMA B-fragments loaded directly from global (volatile).
// Phase 1 computes r only; phase 2 computes o (on h*r) and u (reusing the
// retained h fragments). 128 CTAs = 32 col-groups (16 j) x 4 batch-groups
// (8 b); two release/acquire barriers per step scoped to 32-CTA groups.
// ============================================================================

__device__ __forceinline__ void bg_barrier(unsigned* ctr, unsigned target) {
    __syncthreads();
    if (threadIdx.x == 0) {
        unsigned old;
        asm volatile("atom.release.gpu.global.add.u32 %0, [%1], 1;"
                     : "=r"(old) : "l"(ctr) : "memory");
        unsigned v;
        do {
            asm volatile("ld.acquire.gpu.global.u32 %0, [%1];"
                         : "=r"(v) : "l"(ctr) : "memory");
        } while (v < target);
    }
    __syncthreads();
}

__device__ __forceinline__ float2 ldvol2(const float* p) {
    float2 v;
    asm volatile("ld.volatile.global.v2.f32 {%0,%1}, [%2];"
                 : "=f"(v.x), "=f"(v.y) : "l"(p) : "memory");
    return v;
}
__device__ __forceinline__ float ldvol1(const float* p) {
    float v;
    asm volatile("ld.volatile.global.f32 %0, [%1];" : "=f"(v) : "l"(p) : "memory");
    return v;
}

__global__ __launch_bounds__(512, 1) void scan_kernel(
    int layer,
    const float* __restrict__ Wr_l, const float* __restrict__ Wu_l,
    const float* __restrict__ Wo_l,
    float* __restrict__ dout)
{
    __shared__ float red[16 * 256];   // 16 KB: split-K partials

    int tid = threadIdx.x;
    int cg = blockIdx.x >> 2;    // column group: j in [cg*16, cg*16+16)
    int bg = blockIdx.x & 3;     // batch group:  b in [bg*8,  bg*8+8)
    unsigned* ctr = &g_bar[bg * 32];

    int w = tid >> 5, lane = tid & 31;
    int q = lane & 3;            // frag quad
    int r = lane >> 2;           // frag row / batch
    int k0 = 32 * w;             // this warp's k-slice of the recurrent half

    // ---- step-invariant weight fragments (bf16-split), registers only ----
    unsigned arh[2][4], arl[2][4], auh[2][4], aul[2][4], aoh[2][4], aol[2][4];
#pragma unroll
    for (int ks = 0; ks < 2; ks++)
#pragma unroll
        for (int i = 0; i < 4; i++) {
            int row = cg * 16 + r + 8 * (i & 1);
            int col = 512 + k0 + 16 * ks + 2 * q + 8 * (i >> 1);
            float2 vr = *(const float2*)(Wr_l + (size_t)row * 1024 + col);
            float2 vu = *(const float2*)(Wu_l + (size_t)row * 1024 + col);
            float2 vo = *(const float2*)(Wo_l + (size_t)row * 1024 + col);
            pack_split(vr.x, vr.y, arh[ks][i], arl[ks][i]);
            pack_split(vu.x, vu.y, auh[ks][i], aul[ks][i]);
            pack_split(vo.x, vo.y, aoh[ks][i], aol[ks][i]);
        }

    // per-thread (j,b) output mapping for tid < 128
    int jl = tid >> 3, bloc = tid & 7;
    int j = cg * 16 + jl;
    int bglob = bg * 8 + bloc;

    if (tid < 128) g_hbuf[0][bglob * 512 + j] = 0.f;
    unsigned gen = 0;
    bg_barrier(ctr, (++gen) * 32);

    int cur = 0;
    for (int t = 0; t < 512; t++) {
        // ---- per-thread scalar prefetch (XP + h_old) ----
        float xp_u = 0.f, xp_r = 0.f, xp_o = 0.f, h_old = 0.f;
        if (tid < 128) {
            size_t m = (size_t)t * 32 + bglob;
            const float* xp = g_XP + m * 1536 + j;
            xp_u = __ldg(xp);
            xp_r = __ldg(xp + 512);
            xp_o = __ldg(xp + 1024);
            h_old = ldvol1(&g_hbuf[cur][bglob * 512 + j]);
        }

        // ---- B fragments of h, straight from global (retained for u) ----
        unsigned bh1[2][2], bl1[2][2];
#pragma unroll
        for (int ks = 0; ks < 2; ks++) {
            const float* hp = &g_hbuf[cur][(bg * 8 + r) * 512 + k0 + 16 * ks + 2 * q];
            float2 v0 = ldvol2(hp);
            float2 v1 = ldvol2(hp + 8);
            pack_split(v0.x, v0.y, bh1[ks][0], bl1[ks][0]);
            pack_split(v1.x, v1.y, bh1[ks][1], bl1[ks][1]);
        }

        // ---- phase 1: r gate only (C[16 j][8 b], split-K 16) ----
        float c1[4] = {0.f, 0.f, 0.f, 0.f};
#pragma unroll
        for (int ks = 0; ks < 2; ks++) {
            mma_bf16(c1, arh[ks], bh1[ks]);
            mma_bf16(c1, arh[ks], bl1[ks]);
            mma_bf16(c1, arl[ks], bh1[ks]);
        }
        {
            float* rp = red + w * 128 + r * 8 + 2 * q;
            *(float2*)rp = make_float2(c1[0], c1[1]);
            *(float2*)(rp + 64) = make_float2(c1[2], c1[3]);
        }
        __syncthreads();
        if (tid < 128) {
            float s = 0.f;
#pragma unroll
            for (int ww = 0; ww < 16; ww++) s += red[ww * 128 + tid];
            float rr = 1.f / (1.f + expf(-(s + xp_r)));
            g_hr[bglob * 512 + j] = h_old * rr;
        }
        bg_barrier(ctr, (++gen) * 32);

        // ---- phase 2: o on h*r (fresh frags) + u on h (retained frags) ----
        unsigned bh2[2][2], bl2[2][2];
#pragma unroll
        for (int ks = 0; ks < 2; ks++) {
            const float* hp = &g_hr[(bg * 8 + r) * 512 + k0 + 16 * ks + 2 * q];
            float2 v0 = ldvol2(hp);
            float2 v1 = ldvol2(hp + 8);
            pack_split(v0.x, v0.y, bh2[ks][0], bl2[ks][0]);
            pack_split(v1.x, v1.y, bh2[ks][1], bl2[ks][1]);
        }
        float cu[4] = {0.f, 0.f, 0.f, 0.f};
        float co[4] = {0.f, 0.f, 0.f, 0.f};
#pragma unroll
        for (int ks = 0; ks < 2; ks++) {
            mma_bf16(cu, auh[ks], bh1[ks]);
            mma_bf16(cu, auh[ks], bl1[ks]);
            mma_bf16(cu, aul[ks], bh1[ks]);
            mma_bf16(co, aoh[ks], bh2[ks]);
            mma_bf16(co, aoh[ks], bl2[ks]);
            mma_bf16(co, aol[ks], bh2[ks]);
        }
        {
            float* rp = red + w * 256 + r * 8 + 2 * q;
            *(float2*)rp = make_float2(cu[0], cu[1]);
            *(float2*)(rp + 64) = make_float2(cu[2], cu[3]);
            *(float2*)(rp + 128) = make_float2(co[0], co[1]);
            *(float2*)(rp + 192) = make_float2(co[2], co[3]);
        }
        __syncthreads();
        if (tid < 128) {
            float su = 0.f, so = 0.f;
#pragma unroll
            for (int ww = 0; ww < 16; ww++) {
                su += red[ww * 256 + tid];
                so += red[ww * 256 + 128 + tid];
            }
            float u  = 1.f / (1.f + expf(-(su + xp_u)));
            float ov = tanhf(so + xp_o);
            float hn = fmaf(u, ov - h_old, h_old);    // h*(1-u) + o*u
            g_hbuf[cur ^ 1][bglob * 512 + j] = hn;
            if (layer == 0) g_Hseq[((size_t)t * 32 + bglob) * 512 + j] = hn;
            if (t == 511) dout[layer * 16384 + bglob * 512 + j] = hn;
        }
        bg_barrier(ctr, (++gen) * 32);
        cur ^= 1;
    }
}

// ============================================================================
extern "C" void kernel_launch(void* const* d_in, const int* in_sizes, int n_in,
                              void* d_out, int out_size)
{
    (void)in_sizes; (void)n_in; (void)out_size;
    const float* x  = (const float*)d_in[0];
    const float* Wr = (const float*)d_in[1];
    const float* br = (const float*)d_in[2];
    const float* Wu = (const float*)d_in[3];
    const float* bu = (const float*)d_in[4];
    const float* Wo = (const float*)d_in[5];
    const float* bo = (const float*)d_in[6];
    float* out = (float*)d_out;

    for (int l = 0; l < 2; l++) {
        size_t woff = (size_t)l * 512 * 1024;
        convA_kernel<<<8192, 256>>>(x, l);   // block 0 also resets g_bar
        convW_kernel<<<768, 256>>>(Wr + woff, Wu + woff, Wo + woff);
        xproj_mma_kernel<<<dim3(128, 24), 256>>>(br + l * 512, bu + l * 512, bo + l * 512);
        scan_kernel<<<128, 512, 0>>>(l, Wr + woff, Wu + woff, Wo + woff, out);
    }
}

// round 13
// speedup vs baseline: 1.4653x; 1.0173x over previous
#include <cuda_runtime.h>
#include <cuda_bf16.h>
#include <math.h>

// Problem constants: B=32, T=512, D=H=512, L=2
// Inputs (metadata order): x, Wr, br, Wu, bu, Wo, bo
// Output: (L, B, H) float32 = 32768 elements.

// ---------------- device scratch (no cudaMalloc allowed) ----------------
__device__ float    g_XP[(size_t)16384 * 1536];   // x-projections [m=t*32+b][n=g*512+j]
__device__ float    g_Hseq[(size_t)16384 * 512];  // layer-0 hidden sequence
__device__ float    g_hbuf[2][32 * 512];          // ping-pong h, [b][j]
__device__ float    g_hr[32 * 512];               // h*r exchange, [b][j]
// point-to-point flags: [bg][cg], each padded to 128B. Monotonic counters.
__device__ unsigned g_flagH[4 * 32 * 32];
__device__ unsigned g_flagR[4 * 32 * 32];

// bf16-split scratch for tensor-core xproj
__device__ __nv_bfloat16 g_Ah[(size_t)16384 * 512];
__device__ __nv_bfloat16 g_Al[(size_t)16384 * 512];
__device__ __nv_bfloat16 g_Wh[(size_t)3 * 512 * 512];
__device__ __nv_bfloat16 g_Wl[(size_t)3 * 512 * 512];

// ============================================================================
// fp32 -> (bf16 hi, bf16 lo) split helpers
// ============================================================================
__device__ __forceinline__ void split_bf16(float v, __nv_bfloat16& hi, __nv_bfloat16& lo) {
    hi = __float2bfloat16(v);
    lo = __float2bfloat16(v - __bfloat162float(hi));
}

__device__ __forceinline__ void pack_split(float x0, float x1, unsigned& hi, unsigned& lo) {
    __nv_bfloat16 h0, h1, l0, l1;
    split_bf16(x0, h0, l0);
    split_bf16(x1, h1, l1);
    hi = ((unsigned)__bfloat16_as_ushort(h1) << 16) | (unsigned)__bfloat16_as_ushort(h0);
    lo = ((unsigned)__bfloat16_as_ushort(l1) << 16) | (unsigned)__bfloat16_as_ushort(l0);
}

// A matrix conv: 16384 x 512. amode 0: from x[b][t][k] (m=t*32+b). amode 1: from g_Hseq.
// Blocks 0..15 also reset the scan flags (stream-ordered, replay-safe).
__global__ __launch_bounds__(256) void convA_kernel(const float* __restrict__ x, int amode) {
    if (blockIdx.x < 16) {
        int f = blockIdx.x * 256 + threadIdx.x;
        g_flagH[f] = 0u;
        g_flagR[f] = 0u;
    }
    size_t idx = ((size_t)blockIdx.x * 256 + threadIdx.x) * 4;
    int m = (int)(idx >> 9);
    int k = (int)(idx & 511);
    const float* src = amode ? (g_Hseq + idx)
                             : (x + ((size_t)(m & 31) * 512 + (m >> 5)) * 512 + k);
    float4 v = *(const float4*)src;
    __nv_bfloat16 h0, h1, h2, h3, l0, l1, l2, l3;
    split_bf16(v.x, h0, l0); split_bf16(v.y, h1, l1);
    split_bf16(v.z, h2, l2); split_bf16(v.w, h3, l3);
    ((__nv_bfloat162*)(g_Ah + idx))[0] = __nv_bfloat162(h0, h1);
    ((__nv_bfloat162*)(g_Ah + idx))[1] = __nv_bfloat162(h2, h3);
    ((__nv_bfloat162*)(g_Al + idx))[0] = __nv_bfloat162(l0, l1);
    ((__nv_bfloat162*)(g_Al + idx))[1] = __nv_bfloat162(l2, l3);
}

// W x-halves: g (0=u,1=r,2=o) x 512 j x 512 k  (source row stride 1024)
__global__ __launch_bounds__(256) void convW_kernel(
    const float* __restrict__ Wr, const float* __restrict__ Wu, const float* __restrict__ Wo) {
    size_t idx = ((size_t)blockIdx.x * 256 + threadIdx.x) * 4;
    int g = (int)(idx >> 18);
    int r = (int)(idx & 262143);
    int j = r >> 9, k = r & 511;
    const float* W = (g == 0) ? Wu : (g == 1) ? Wr : Wo;
    float4 v = *(const float4*)(W + (size_t)j * 1024 + k);
    __nv_bfloat16 h0, h1, h2, h3, l0, l1, l2, l3;
    split_bf16(v.x, h0, l0); split_bf16(v.y, h1, l1);
    split_bf16(v.z, h2, l2); split_bf16(v.w, h3, l3);
    ((__nv_bfloat162*)(g_Wh + idx))[0] = __nv_bfloat162(h0, h1);
    ((__nv_bfloat162*)(g_Wh + idx))[1] = __nv_bfloat162(h2, h3);
    ((__nv_bfloat162*)(g_Wl + idx))[0] = __nv_bfloat162(l0, l1);
    ((__nv_bfloat162*)(g_Wl + idx))[1] = __nv_bfloat162(l2, l3);
}

// ============================================================================
// mma.sync m16n8k16 bf16 (row.col, fp32 accum) + ldmatrix
// ============================================================================
__device__ __forceinline__ void mma_bf16(float* c, const unsigned* a, const unsigned* b) {
    asm volatile("mma.sync.aligned.m16n8k16.row.col.f32.bf16.bf16.f32 "
                 "{%0,%1,%2,%3}, {%4,%5,%6,%7}, {%8,%9}, {%0,%1,%2,%3};"
                 : "+f"(c[0]), "+f"(c[1]), "+f"(c[2]), "+f"(c[3])
                 : "r"(a[0]), "r"(a[1]), "r"(a[2]), "r"(a[3]), "r"(b[0]), "r"(b[1]));
}

__device__ __forceinline__ void ldsm_x4(unsigned& r0, unsigned& r1, unsigned& r2, unsigned& r3,
                                        const __nv_bfloat16* p) {
    unsigned a = (unsigned)__cvta_generic_to_shared(p);
    asm volatile("ldmatrix.sync.aligned.m8n8.x4.shared.b16 {%0,%1,%2,%3}, [%4];"
                 : "=r"(r0), "=r"(r1), "=r"(r2), "=r"(r3) : "r"(a));
}

// ============================================================================
// Tensor-core xproj (unchanged, ~265us/layer)
// ============================================================================
#define SM_PITCH 40

__global__ __launch_bounds__(256) void xproj_mma_kernel(
    const float* __restrict__ br, const float* __restrict__ bu, const float* __restrict__ bo) {
    __shared__ __nv_bfloat16 Ah_s[128][SM_PITCH];
    __shared__ __nv_bfloat16 Al_s[128][SM_PITCH];
    __shared__ __nv_bfloat16 Wh_s[64][SM_PITCH];
    __shared__ __nv_bfloat16 Wl_s[64][SM_PITCH];

    int tid = threadIdx.x;
    int m0 = blockIdx.x * 128;
    int n0 = blockIdx.y * 64;
    int g = n0 >> 9, j0 = n0 & 511;
    const float* bv = (g == 0) ? bu : (g == 1) ? br : bo;

    int w = tid >> 5, lane = tid & 31;
    int wm = w >> 1, wn = w & 1;

    float acc[2][4][4];
#pragma unroll
    for (int mf = 0; mf < 2; mf++)
#pragma unroll
        for (int nf = 0; nf < 4; nf++)
#pragma unroll
            for (int i = 0; i < 4; i++) acc[mf][nf][i] = 0.f;

    for (int k0 = 0; k0 < 512; k0 += 32) {
#pragma unroll
        for (int q = 0; q < 2; q++) {
            int u = q * 256 + tid;
            int row = u >> 2, c8 = (u & 3) * 8;
            size_t go = (size_t)(m0 + row) * 512 + k0 + c8;
            *(uint4*)&Ah_s[row][c8] = *(const uint4*)(g_Ah + go);
            *(uint4*)&Al_s[row][c8] = *(const uint4*)(g_Al + go);
        }
        {
            int row = tid >> 2, c8 = (tid & 3) * 8;
            size_t go = ((size_t)g * 512 + j0 + row) * 512 + k0 + c8;
            *(uint4*)&Wh_s[row][c8] = *(const uint4*)(g_Wh + go);
            *(uint4*)&Wl_s[row][c8] = *(const uint4*)(g_Wl + go);
        }
        __syncthreads();

#pragma unroll
        for (int k16 = 0; k16 < 32; k16 += 16) {
            unsigned ah[2][4], al[2][4], bh[4][2], bl[4][2];
            int arow = wm * 32 + (lane & 15);
            int acol = k16 + (lane >> 4) * 8;
#pragma unroll
            for (int mf = 0; mf < 2; mf++) {
                ldsm_x4(ah[mf][0], ah[mf][1], ah[mf][2], ah[mf][3], &Ah_s[arow + mf * 16][acol]);
                ldsm_x4(al[mf][0], al[mf][1], al[mf][2], al[mf][3], &Al_s[arow + mf * 16][acol]);
            }
            int brow_ = ((lane & 16) >> 1) + (lane & 7);
            int bcol = k16 + ((lane >> 3) & 1) * 8;
#pragma unroll
            for (int nh = 0; nh < 2; nh++) {
                int rr = wn * 32 + nh * 16 + brow_;
                ldsm_x4(bh[nh * 2][0], bh[nh * 2][1], bh[nh * 2 + 1][0], bh[nh * 2 + 1][1],
                        &Wh_s[rr][bcol]);
                ldsm_x4(bl[nh * 2][0], bl[nh * 2][1], bl[nh * 2 + 1][0], bl[nh * 2 + 1][1],
                        &Wl_s[rr][bcol]);
            }
#pragma unroll
            for (int mf = 0; mf < 2; mf++)
#pragma unroll
                for (int nf = 0; nf < 4; nf++) {
                    mma_bf16(acc[mf][nf], ah[mf], bh[nf]);
                    mma_bf16(acc[mf][nf], ah[mf], bl[nf]);
                    mma_bf16(acc[mf][nf], al[mf], bh[nf]);
                }
        }
        __syncthreads();
    }

#pragma unroll
    for (int nf = 0; nf < 4; nf++) {
        int jc = j0 + wn * 32 + nf * 8 + (lane & 3) * 2;
        float b0 = __ldg(bv + jc), b1 = __ldg(bv + jc + 1);
        int ncol = n0 + wn * 32 + nf * 8 + (lane & 3) * 2;
#pragma unroll
        for (int mf = 0; mf < 2; mf++) {
            int r0 = m0 + wm * 32 + mf * 16 + (lane >> 2);
            float2 v0 = make_float2(acc[mf][nf][0] + b0, acc[mf][nf][1] + b1);
            float2 v1 = make_float2(acc[mf][nf][2] + b0, acc[mf][nf][3] + b1);
            *(float2*)(g_XP + (size_t)r0 * 1536 + ncol) = v0;
            *(float2*)(g_XP + (size_t)(r0 + 8) * 1536 + ncol) = v1;
        }
    }
}

// ============================================================================
// Persistent scan kernel — point-to-point flag sync (no global barriers).
// 128 CTAs = 32 col-groups (16 j) x 4 batch-groups (8 b). Per step:
//   phase A: warps wait h-flags of their 2 producer CTAs, compute r,
//            publish h*r slice + bump flagR[cg].
//   phase B: warps wait hr-flags of their 2 producers, compute o (+u on
//            retained h frags), publish h_new slice + bump flagH[cg].
// Flags are monotonic per-(bg,cg) counters; h ping-pong prevents WAR.
// ============================================================================

__device__ __forceinline__ void wait_flag(const unsigned* f, unsigned target) {
    unsigned v;
    do {
        asm volatile("ld.acquire.gpu.global.u32 %0, [%1];" : "=r"(v) : "l"(f) : "memory");
    } while (v < target);
}

__device__ __forceinline__ void bump_flag(unsigned* f) {
    unsigned old;
    asm volatile("atom.release.gpu.global.add.u32 %0, [%1], 1;"
                 : "=r"(old) : "l"(f) : "memory");
}

__device__ __forceinline__ float2 ldvol2(const float* p) {
    float2 v;
    asm volatile("ld.volatile.global.v2.f32 {%0,%1}, [%2];"
                 : "=f"(v.x), "=f"(v.y) : "l"(p) : "memory");
    return v;
}

__global__ __launch_bounds__(512, 1) void scan_kernel(
    int layer,
    const float* __restrict__ Wr_l, const float* __restrict__ Wu_l,
    const float* __restrict__ Wo_l,
    float* __restrict__ dout)
{
    __shared__ float red[16 * 256];   // 16 KB split-K partials

    int tid = threadIdx.x;
    int cg = blockIdx.x >> 2;    // column group: j in [cg*16, cg*16+16)
    int bg = blockIdx.x & 3;     // batch group:  b in [bg*8,  bg*8+8)

    unsigned* flagH = &g_flagH[bg * 32 * 32];   // + cg*32
    unsigned* flagR = &g_flagR[bg * 32 * 32];

    int w = tid >> 5, lane = tid & 31;
    int q = lane & 3;
    int r = lane >> 2;
    int k0 = 32 * w;             // this warp's k-slice of the recurrent half
    int pcg = 2 * w + (lane & 1);   // producer cg polled by lanes 0/1

    // ---- step-invariant weight fragments (bf16-split), registers only ----
    unsigned arh[2][4], arl[2][4], auh[2][4], aul[2][4], aoh[2][4], aol[2][4];
#pragma unroll
    for (int ks = 0; ks < 2; ks++)
#pragma unroll
        for (int i = 0; i < 4; i++) {
            int row = cg * 16 + r + 8 * (i & 1);
            int col = 512 + k0 + 16 * ks + 2 * q + 8 * (i >> 1);
            float2 vr = *(const float2*)(Wr_l + (size_t)row * 1024 + col);
            float2 vu = *(const float2*)(Wu_l + (size_t)row * 1024 + col);
            float2 vo = *(const float2*)(Wo_l + (size_t)row * 1024 + col);
            pack_split(vr.x, vr.y, arh[ks][i], arl[ks][i]);
            pack_split(vu.x, vu.y, auh[ks][i], aul[ks][i]);
            pack_split(vo.x, vo.y, aoh[ks][i], aol[ks][i]);
        }

    // per-thread (j,b) output mapping for tid < 128
    int jl = tid >> 3, bloc = tid & 7;
    int j = cg * 16 + jl;
    int bglob = bg * 8 + bloc;

    // publish h0 = 0 (flagH -> 1)
    float h_old = 0.f;
    if (tid < 128) g_hbuf[0][bglob * 512 + j] = 0.f;
    __syncthreads();
    if (tid == 0) bump_flag(&flagH[cg * 32]);

    int cur = 0;
    for (int t = 0; t < 512; t++) {
        // ---- per-thread XP prefetch (independent of flags) ----
        float xp_u = 0.f, xp_r = 0.f, xp_o = 0.f;
        if (tid < 128) {
            size_t m = (size_t)t * 32 + bglob;
            const float* xp = g_XP + m * 1536 + j;
            xp_u = __ldg(xp);
            xp_r = __ldg(xp + 512);
            xp_o = __ldg(xp + 1024);
        }

        // ---- phase A: wait producers of this warp's h k-slice ----
        if (lane < 2) wait_flag(&flagH[pcg * 32], (unsigned)(t + 1));
        __syncwarp();

        unsigned bh1[2][2], bl1[2][2];
#pragma unroll
        for (int ks = 0; ks < 2; ks++) {
            const float* hp = &g_hbuf[cur][(bg * 8 + r) * 512 + k0 + 16 * ks + 2 * q];
            float2 v0 = ldvol2(hp);
            float2 v1 = ldvol2(hp + 8);
            pack_split(v0.x, v0.y, bh1[ks][0], bl1[ks][0]);
            pack_split(v1.x, v1.y, bh1[ks][1], bl1[ks][1]);
        }

        float c1[4] = {0.f, 0.f, 0.f, 0.f};
#pragma unroll
        for (int ks = 0; ks < 2; ks++) {
            mma_bf16(c1, arh[ks], bh1[ks]);
            mma_bf16(c1, arh[ks], bl1[ks]);
            mma_bf16(c1, arl[ks], bh1[ks]);
        }
        {
            float* rp = red + w * 128 + r * 8 + 2 * q;
            *(float2*)rp = make_float2(c1[0], c1[1]);
            *(float2*)(rp + 64) = make_float2(c1[2], c1[3]);
        }
        __syncthreads();
        if (tid < 128) {
            float s = 0.f;
#pragma unroll
            for (int ww = 0; ww < 16; ww++) s += red[ww * 128 + tid];
            float rr = 1.f / (1.f + expf(-(s + xp_r)));
            g_hr[bglob * 512 + j] = h_old * rr;
        }
        __syncthreads();
        if (tid == 0) bump_flag(&flagR[cg * 32]);

        // ---- phase B: wait producers of this warp's h*r k-slice ----
        if (lane < 2) wait_flag(&flagR[pcg * 32], (unsigned)(t + 1));
        __syncwarp();

        unsigned bh2[2][2], bl2[2][2];
#pragma unroll
        for (int ks = 0; ks < 2; ks++) {
            const float* hp = &g_hr[(bg * 8 + r) * 512 + k0 + 16 * ks + 2 * q];
            float2 v0 = ldvol2(hp);
            float2 v1 = ldvol2(hp + 8);
            pack_split(v0.x, v0.y, bh2[ks][0], bl2[ks][0]);
            pack_split(v1.x, v1.y, bh2[ks][1], bl2[ks][1]);
        }
        float cu[4] = {0.f, 0.f, 0.f, 0.f};
        float co[4] = {0.f, 0.f, 0.f, 0.f};
#pragma unroll
        for (int ks = 0; ks < 2; ks++) {
            mma_bf16(cu, auh[ks], bh1[ks]);
            mma_bf16(cu, auh[ks], bl1[ks]);
            mma_bf16(cu, aul[ks], bh1[ks]);
            mma_bf16(co, aoh[ks], bh2[ks]);
            mma_bf16(co, aoh[ks], bl2[ks]);
            mma_bf16(co, aol[ks], bh2[ks]);
        }
        {
            float* rp = red + w * 256 + r * 8 + 2 * q;
            *(float2*)rp = make_float2(cu[0], cu[1]);
            *(float2*)(rp + 64) = make_float2(cu[2], cu[3]);
            *(float2*)(rp + 128) = make_float2(co[0], co[1]);
            *(float2*)(rp + 192) = make_float2(co[2], co[3]);
        }
        __syncthreads();
        if (tid < 128) {
            float su = 0.f, so = 0.f;
#pragma unroll
            for (int ww = 0; ww < 16; ww++) {
                su += red[ww * 256 + tid];
                so += red[ww * 256 + 128 + tid];
            }
            float u  = 1.f / (1.f + expf(-(su + xp_u)));
            float ov = tanhf(so + xp_o);
            float hn = fmaf(u, ov - h_old, h_old);    // h*(1-u) + o*u
            h_old = hn;
            g_hbuf[cur ^ 1][bglob * 512 + j] = hn;
            if (layer == 0) g_Hseq[((size_t)t * 32 + bglob) * 512 + j] = hn;
            if (t == 511) dout[layer * 16384 + bglob * 512 + j] = hn;
        }
        __syncthreads();
        if (tid == 0) bump_flag(&flagH[cg * 32]);
        cur ^= 1;
    }
}

// ============================================================================
extern "C" void kernel_launch(void* const* d_in, const int* in_sizes, int n_in,
                              void* d_out, int out_size)
{
    (void)in_sizes; (void)n_in; (void)out_size;
    const float* x  = (const float*)d_in[0];
    const float* Wr = (const float*)d_in[1];
    const float* br = (const float*)d_in[2];
    const float* Wu = (const float*)d_in[3];
    const float* bu = (const float*)d_in[4];
    const float* Wo = (const float*)d_in[5];
    const float* bo = (const float*)d_in[6];
    float* out = (float*)d_out;

    for (int l = 0; l < 2; l++) {
        size_t woff = (size_t)l * 512 * 1024;
        convA_kernel<<<8192, 256>>>(x, l);   // blocks 0..15 also reset flags
        convW_kernel<<<768, 256>>>(Wr + woff, Wu + woff, Wo + woff);
        xproj_mma_kernel<<<dim3(128, 24), 256>>>(br + l * 512, bu + l * 512, bo + l * 512);
        scan_kernel<<<128, 512, 0>>>(l, Wr + woff, Wu + woff, Wo + woff, out);
    }
}